// round 14
// baseline (speedup 1.0000x reference)
#include <cuda_runtime.h>
#include <cuda_fp16.h>
#include <cstdint>

// B=256, T=512, H=1024 LSTM decoder on sm_103a (PTX baseline sm_103: no tcgen05).
// Single persistent kernel. 128 CTAs in 32 clusters of 4.
// 16 compute warps (4M x 4N, 32x16 warp tiles) + 1 producer warp = 544 thr.
// mma.sync m16n8k16 fp16/fp32, cross-chunk register pipelining, STATIC slots.
// A (h) chunks via cp.async.bulk + multicast::cluster from a pre-swizzled
// global h image, sequential chunk order. W resident in SMEM with a
// gate-permuted row map so the epilogue is shfl-free per lane.
// No per-step global barrier: monotonic per-cluster counters g_ready[q].

static constexpr int Tn = 512, Bn = 256, Hn = 1024;
static constexpr int GRID = 128, NTHR = 544;   // 16 compute warps + 1 producer
static constexpr int NCHUNK = 16;              // K chunks of 64 halfs
static constexpr int CHUNK_B = 16384;          // per-CTA A chunk: 128 rows x 128B
static constexpr int SLICE_B = 4096;           // per-rank multicast slice (32 rows)
static constexpr int IMG_CHUNK = 32768;        // image chunk: 256 rows x 128B
static constexpr int B_STR = 1032;             // W smem stride in halfs (padded)
static constexpr unsigned NPHASE = 2;          // initial + final global barriers

static constexpr int OFF_FULL = 0;             // 4 mbarriers
static constexpr int OFF_DONE = 32;            // 4 mbarriers
static constexpr int OFF_BIAS = 128;           // 64 f32
static constexpr int OFF_WIN  = 384;           // 64 f32
static constexpr int OFF_A    = 1024;          // 4 x 16KB A buffers
static constexpr int OFF_W    = OFF_A + 4 * CHUNK_B;        // 66560
static constexpr int SMEM_SZ  = OFF_W + 64 * B_STR * 2;     // 198656

__device__ __align__(1024) unsigned char g_himg[2][NCHUNK * IMG_CHUNK];
__device__ float    g_ytr[Tn * Bn];
__device__ unsigned g_bar;        // monotonic across graph replays
__device__ unsigned g_epoch;      // g_bar base for current launch
__device__ unsigned g_ready[64];  // per-cluster h-ready counters (monotonic)
__device__ unsigned g_epochR;     // g_ready base for current launch

#define SWZ(off) ((off) ^ (((off) >> 3) & 0x70))

// ---------------- helpers ----------------
__device__ __forceinline__ uint32_t smem_u32(const void* p) {
    uint32_t a;
    asm("{ .reg .u64 t; cvta.to.shared.u64 t, %1; cvt.u32.u64 %0, t; }" : "=r"(a) : "l"(p));
    return a;
}
__device__ __forceinline__ uint32_t elect_one() {
    uint32_t p;
    asm volatile("{ .reg .pred p; elect.sync _|p, 0xFFFFFFFF; selp.b32 %0, 1, 0, p; }" : "=r"(p));
    return p;
}
__device__ __forceinline__ unsigned ld_acquire_gpu(const unsigned* p) {
    unsigned v;
    asm volatile("ld.acquire.gpu.global.u32 %0, [%1];" : "=r"(v) : "l"(p) : "memory");
    return v;
}
#define MBARRIER_INIT(addr, cnt) \
    asm volatile("mbarrier.init.shared.b64 [%0], %1;" :: "r"((uint32_t)(addr)), "r"((uint32_t)(cnt)) : "memory")
#define MBARRIER_EXPECT_TX(addr, tx) \
    asm volatile("mbarrier.arrive.expect_tx.shared.b64 _, [%0], %1;" :: "r"((uint32_t)(addr)), "r"((uint32_t)(tx)) : "memory")
#define ARRIVE_CLUSTER(mbar, r) \
    asm volatile("{ .reg .b32 ra; mapa.shared::cluster.u32 ra, %0, %1; " \
                 "mbarrier.arrive.shared::cluster.b64 _, [ra]; }" \
                 :: "r"((uint32_t)(mbar)), "r"((uint32_t)(r)) : "memory")

__device__ __forceinline__ void mbar_wait(uint32_t mbar, uint32_t parity) {
    asm volatile(
        "{\n\t.reg .pred P;\n\t"
        "LAB_%=:\n\t"
        "mbarrier.try_wait.parity.acquire.cta.shared::cta.b64 P, [%0], %1, 0x989680;\n\t"
        "@!P bra LAB_%=;\n\t}"
        :: "r"(mbar), "r"(parity) : "memory");
}
__device__ __forceinline__ void bulk_mcast(uint32_t dst, const void* src, uint32_t bytes,
                                           uint32_t mbar, uint16_t mask) {
    asm volatile(
        "cp.async.bulk.shared::cluster.global.mbarrier::complete_tx::bytes.multicast::cluster"
        " [%0], [%1], %2, [%3], %4;"
        :: "r"(dst), "l"(src), "r"(bytes), "r"(mbar), "h"(mask) : "memory");
}
#define CLUSTER_ARRIVE() asm volatile("barrier.cluster.arrive.aligned;" ::: "memory")
#define CLUSTER_WAIT()   asm volatile("barrier.cluster.wait.aligned;" ::: "memory")

#define LDSM_X4(r0, r1, r2, r3, addr)                                           \
    asm volatile("ldmatrix.sync.aligned.m8n8.x4.shared.b16 {%0,%1,%2,%3},[%4];" \
                 : "=r"(r0), "=r"(r1), "=r"(r2), "=r"(r3) : "r"(addr))

#define MMA16816(d, a, b0, b1)                                                \
    asm volatile("mma.sync.aligned.m16n8k16.row.col.f32.f16.f16.f32 "         \
                 "{%0,%1,%2,%3},{%4,%5,%6,%7},{%8,%9},{%0,%1,%2,%3};"         \
                 : "+f"((d)[0]), "+f"((d)[1]), "+f"((d)[2]), "+f"((d)[3])     \
                 : "r"((a)[0]), "r"((a)[1]), "r"((a)[2]), "r"((a)[3]),        \
                   "r"(b0), "r"(b1))

__device__ __forceinline__ float tanha(float x) {
    float y; asm("tanh.approx.f32 %0, %1;" : "=f"(y) : "f"(x)); return y;
}
__device__ __forceinline__ float sigt(float x) { return fmaf(tanha(0.5f * x), 0.5f, 0.5f); }

// image byte offset for (row 0..255, half-col k 0..1023)
__device__ __forceinline__ uint32_t img_off(int row, int k) {
    int kc = k >> 6, kl = k & 63;
    uint32_t local = (uint32_t)((row & 7) * 128 + kl * 2);
    return (uint32_t)(kc * IMG_CHUNK + (row >> 3) * 1024) + SWZ(local);
}

// global barrier (used ONLY at start and end): cluster.sync + leader atomic
__device__ __forceinline__ void gbar(int is_leader, unsigned target) {
    __threadfence();
    CLUSTER_ARRIVE(); CLUSTER_WAIT();
    if (is_leader) {
        atomicAdd(&g_bar, 1u);
        while (ld_acquire_gpu(&g_bar) < target) { }
    }
    CLUSTER_ARRIVE(); CLUSTER_WAIT();
}

// W smem row map: row r (0..63) -> gate = ((r>>3)&1) + 2*(r&1),
//                 jj = ((r>>1)&3) + (r>>4)*4
// Gives each lane all 4 gates of its own cell in the MMA output (shfl-free).
__device__ __forceinline__ void w_row_map(int r, int& gate, int& jj) {
    gate = ((r >> 3) & 1) + 2 * (r & 1);
    jj   = ((r >> 1) & 3) + (r >> 4) * 4;
}

// ---------------- the single persistent kernel ----------------
__global__ void __launch_bounds__(NTHR, 1)
lstm_persist(const float* __restrict__ y_hist, const float* __restrict__ W_ih,
             const float* __restrict__ W_hh,   const float* __restrict__ b_ih,
             const float* __restrict__ b_hh,   const float* __restrict__ W_fc,
             const float* __restrict__ b_fc,   const float* __restrict__ h0,
             const float* __restrict__ c0,     float* __restrict__ out) {
    extern __shared__ char smem[];
    const uint32_t sb = smem_u32(smem);
    float* bias_s = (float*)(smem + OFF_BIAS);
    float* win_s  = (float*)(smem + OFF_WIN);

    const int tid = threadIdx.x, lid = tid & 31, wid = tid >> 5;
    const int wm = wid >> 2, wn = wid & 3;              // compute warps: 4M x 4N
    const int bx = blockIdx.x, q = bx >> 2, rank = bx & 3;
    const int mi = q & 1, ci = (q >> 1) * 4 + rank;
    const int m0 = mi * 128, j0 = ci * 16;
    const int is_leader = (rank == 0 && tid == 0);

    const unsigned epoch = g_epoch;    // stable during the launch
    const unsigned ebR   = g_epochR;   // g_ready base for this launch

    if (tid == 0) {
        #pragma unroll
        for (int b = 0; b < 4; ++b) {
            MBARRIER_INIT(sb + OFF_FULL + b * 8, 1);
            MBARRIER_INIT(sb + OFF_DONE + b * 8, 64);   // 16 warps x 4 CTAs
        }
    }
    // bias/w_in indexed by smem W row r
    if (tid < 64) {
        int gate, jj; w_row_map(tid, gate, jj);
        int n = gate * Hn + j0 + jj;
        bias_s[tid] = b_ih[n] + b_hh[n];
        win_s[tid]  = W_ih[n];
    }
    // resident W slice with the permuted row map
    for (int e = tid; e < 64 * Hn / 8; e += NTHR) {
        int r = e >> 7, kg = (e & 127) << 3;
        int gate, jj; w_row_map(r, gate, jj);
        const float* src = W_hh + (size_t)(gate * Hn + j0 + jj) * Hn + kg;
        float4 f0 = *(const float4*)src;
        float4 f1 = *(const float4*)(src + 4);
        __half hv[8];
        hv[0] = __float2half(f0.x); hv[1] = __float2half(f0.y);
        hv[2] = __float2half(f0.z); hv[3] = __float2half(f0.w);
        hv[4] = __float2half(f1.x); hv[5] = __float2half(f1.y);
        hv[6] = __float2half(f1.z); hv[7] = __float2half(f1.w);
        *(uint4*)(smem + OFF_W + (size_t)(r * B_STR + kg) * 2) = *(const uint4*)hv;
    }

    // -------- folded prologue: y transpose + h0 -> swizzled fp16 image --------
    for (int i = tid; i < 1024; i += NTHR) {
        int idx = bx * 1024 + i;                   // covers Tn*Bn = 131072
        int t = idx >> 8, b = idx & 255;
        g_ytr[idx] = y_hist[(size_t)b * Tn + t];
    }
    for (int i = tid; i < 256; i += NTHR) {
        int u = bx * 256 + i;                      // covers 32768 uint4 units
        int b2 = u >> 7, k = (u & 127) * 8;
        const float* s = h0 + (size_t)b2 * Hn + k;
        __half hv[8];
        #pragma unroll
        for (int j = 0; j < 8; ++j) hv[j] = __float2half(s[j]);
        *(uint4*)(g_himg[0] + img_off(b2, k)) = *(const uint4*)hv;
    }
    __syncthreads();
    gbar(is_leader, epoch + 32u);                  // prologue + mbarrier init visible

    if (wid == 16) {
        // ================= producer: flat (t, chunk) loop =================
        if (elect_one()) {
            const uint32_t src_off = (uint32_t)(mi * 16384 + rank * SLICE_B);
            unsigned n = 0;
            #pragma unroll 1
            for (int t = 0; t < Tn; ++t) {
                const unsigned char* img = g_himg[t & 1];
                const unsigned thr = ebR + 4u * (unsigned)t;
                #pragma unroll 1
                for (int i = 0; i < NCHUNK; ++i, ++n) {
                    int b = (int)(n & 3);
                    if (n >= 4) mbar_wait(sb + OFF_DONE + b * 8, ((n >> 2) - 1) & 1);
                    if (t > 0) {
                        const unsigned* rp = &g_ready[2 * i + mi];
                        while (ld_acquire_gpu(rp) < thr) { }
                    }
                    MBARRIER_EXPECT_TX(sb + OFF_FULL + b * 8, CHUNK_B);
                    bulk_mcast(sb + OFF_A + b * CHUNK_B + rank * SLICE_B,
                               img + i * IMG_CHUNK + src_off, SLICE_B,
                               sb + OFF_FULL + b * 8, 0xF);
                }
            }
        }
    } else {
        // ================= compute warps (32x16 tiles) =================
        const int aRowL = lid & 15;
        const int cgB   = (lid >> 4) * 16;
        int aBase[2], aXor = 0;
        #pragma unroll
        for (int mt = 0; mt < 2; ++mt) {
            int r = wm * 32 + mt * 16 + aRowL;
            aBase[mt] = (r >> 3) * 1024 + (r & 7) * 128;
            aXor = (r & 7) * 16;
        }
        const int bRow  = (lid & 7) + ((lid >> 4) << 3);
        const int bColB = (lid & 8) ? 16 : 0;
        const int bOff  = OFF_W + ((wn * 16 + bRow) * B_STR) * 2 + bColB;

        // cell ownership (shfl-free): lane owns rows mt*16 + (lid>>2) + rr*8,
        // single h-col jc = j0 + wn*4 + (lid&3); 4 gates come from (nt, v&1).
        const int rowA = m0 + wm * 32 + (lid >> 2);
        const int jc   = j0 + wn * 4 + (lid & 3);
        float cst[4];
        #pragma unroll
        for (int mt = 0; mt < 2; ++mt)
            #pragma unroll
            for (int rr = 0; rr < 2; ++rr)
                cst[mt * 2 + rr] = c0[(size_t)(rowA + mt * 16 + rr * 8) * Hn + jc];

        // bias / w_in registers: index [nt][b0] -> smem row wn*16+nt*8+(lid&3)*2+b0
        float wz[2][2], bz[2][2];
        #pragma unroll
        for (int nt = 0; nt < 2; ++nt)
            #pragma unroll
            for (int b0 = 0; b0 < 2; ++b0) {
                int r = wn * 16 + nt * 8 + (lid & 3) * 2 + b0;
                wz[nt][b0] = win_s[r];
                bz[nt][b0] = bias_s[r];
            }

        uint32_t a0[2][4], b0v[4], a1[2][4], b1v[4];

#define LOAD_FRAGS0(ab, ksB, iB) do {                                          \
        _Pragma("unroll")                                                      \
        for (int mt = 0; mt < 2; ++mt)                                         \
            LDSM_X4(a0[mt][0], a0[mt][1], a0[mt][2], a0[mt][3],                \
                    (ab) + aBase[mt] + (((ksB) + cgB) ^ aXor));                \
        LDSM_X4(b0v[0], b0v[1], b0v[2], b0v[3],                                \
                sb + bOff + (iB) * 128 + (ksB));                               \
    } while (0)

#define LOAD_FRAGS1(ab, ksB, iB) do {                                          \
        _Pragma("unroll")                                                      \
        for (int mt = 0; mt < 2; ++mt)                                         \
            LDSM_X4(a1[mt][0], a1[mt][1], a1[mt][2], a1[mt][3],                \
                    (ab) + aBase[mt] + (((ksB) + cgB) ^ aXor));                \
        LDSM_X4(b1v[0], b1v[1], b1v[2], b1v[3],                                \
                sb + bOff + (iB) * 128 + (ksB));                               \
    } while (0)

#define DO_MMAS0() do {                                                        \
        _Pragma("unroll")                                                      \
        for (int mt = 0; mt < 2; ++mt) {                                       \
            MMA16816(d[mt][0], a0[mt], b0v[0], b0v[1]);                        \
            MMA16816(d[mt][1], a0[mt], b0v[2], b0v[3]);                        \
        }                                                                      \
    } while (0)

#define DO_MMAS1() do {                                                        \
        _Pragma("unroll")                                                      \
        for (int mt = 0; mt < 2; ++mt) {                                       \
            MMA16816(d[mt][0], a1[mt], b1v[0], b1v[1]);                        \
            MMA16816(d[mt][1], a1[mt], b1v[2], b1v[3]);                        \
        }                                                                      \
    } while (0)

        unsigned n = 0;
        #pragma unroll 1
        for (int t = 0; t < Tn; ++t) {
            float xv[2][2];
            #pragma unroll
            for (int mt = 0; mt < 2; ++mt) {
                int rb = t * Bn + rowA + mt * 16;
                xv[mt][0] = __ldg(&g_ytr[rb]);
                xv[mt][1] = __ldg(&g_ytr[rb + 8]);
            }

            float d[2][2][4] = {};

            // step head: wait chunk 0, preload its ks0 frags into slot 0
            mbar_wait(sb + OFF_FULL + (n & 3) * 8, (n >> 2) & 1);
            LOAD_FRAGS0(sb + OFF_A + (n & 3) * CHUNK_B, 0, 0);

            // invariant at each chunk head: slot0 holds this chunk's ks0 frags
            #pragma unroll 1
            for (int i = 0; i < NCHUNK; ++i, ++n) {
                const uint32_t ab = sb + OFF_A + (n & 3) * CHUNK_B;
                LOAD_FRAGS1(ab, 32, i);  DO_MMAS0();   // ks0
                LOAD_FRAGS0(ab, 64, i);  DO_MMAS1();   // ks1
                LOAD_FRAGS1(ab, 96, i);  DO_MMAS0();   // ks2
                if (i < NCHUNK - 1) {
                    mbar_wait(sb + OFF_FULL + ((n + 1) & 3) * 8, ((n + 1) >> 2) & 1);
                    LOAD_FRAGS0(sb + OFF_A + ((n + 1) & 3) * CHUNK_B, 0, i + 1);
                }
                DO_MMAS1();                             // ks3 (slot1 consumed)
                if (elect_one()) {
                    ARRIVE_CLUSTER(sb + OFF_DONE + (n & 3) * 8, 0);
                    ARRIVE_CLUSTER(sb + OFF_DONE + (n & 3) * 8, 1);
                    ARRIVE_CLUSTER(sb + OFF_DONE + (n & 3) * 8, 2);
                    ARRIVE_CLUSTER(sb + OFF_DONE + (n & 3) * 8, 3);
                }
            }

            // epilogue (shfl-free): gates = (nt, v&1); 4 cells per lane
            unsigned char* img1 = g_himg[(t + 1) & 1];
            #pragma unroll
            for (int mt = 0; mt < 2; ++mt) {
                #pragma unroll
                for (int rr = 0; rr < 2; ++rr) {
                    float x = xv[mt][rr];
                    float gi = d[mt][0][rr * 2 + 0] + x * wz[0][0] + bz[0][0];
                    float gf = d[mt][1][rr * 2 + 0] + x * wz[1][0] + bz[1][0];
                    float gg = d[mt][0][rr * 2 + 1] + x * wz[0][1] + bz[0][1];
                    float go = d[mt][1][rr * 2 + 1] + x * wz[1][1] + bz[1][1];
                    float cn = sigt(gf) * cst[mt * 2 + rr] + sigt(gi) * tanha(gg);
                    cst[mt * 2 + rr] = cn;
                    float hn = sigt(go) * tanha(cn);
                    *(__half*)(img1 + img_off(rowA + mt * 16 + rr * 8, jc)) =
                        __float2half(hn);
                }
            }

            // publish h(t+1): fence own stores, sync 16 compute warps, 1 atomic
            __threadfence();
            asm volatile("bar.sync 1, 512;" ::: "memory");
            if (tid == 0) atomicAdd(&g_ready[q], 1u);
        }
#undef LOAD_FRAGS0
#undef LOAD_FRAGS1
#undef DO_MMAS0
#undef DO_MMAS1
    }

    // -------- final global barrier + folded FC --------
    gbar(is_leader, epoch + 64u);

    if (wid < 2) {
        int r = bx * 2 + wid;
        float acc = 0.0f;
        #pragma unroll
        for (int it = 0; it < 4; ++it) {
            int kc = it * 4 + (lid >> 3), u = lid & 7;
            const __half* p = (const __half*)(g_himg[0] + img_off(r, kc * 64 + u * 8));
            const float* w = W_fc + kc * 64 + u * 8;
            #pragma unroll
            for (int j = 0; j < 8; ++j) acc += __half2float(p[j]) * w[j];
        }
        #pragma unroll
        for (int o = 16; o; o >>= 1) acc += __shfl_xor_sync(~0u, acc, o);
        if (lid == 0) out[r] = acc + b_fc[0];
    }

    // advance epochs for the next launch (all adds for this launch complete)
    if (bx == 0 && tid == 0) {
        g_epoch  = epoch + 32u * NPHASE;
        g_epochR = ebR + 4u * (unsigned)Tn;
    }
}

extern "C" void kernel_launch(void* const* d_in, const int* in_sizes, int n_in,
                              void* d_out, int out_size) {
    const float* y_hist = (const float*)d_in[0];
    const float* W_ih   = (const float*)d_in[1];
    const float* W_hh   = (const float*)d_in[2];
    const float* b_ih   = (const float*)d_in[3];
    const float* b_hh   = (const float*)d_in[4];
    const float* W_fc   = (const float*)d_in[5];
    const float* b_fc   = (const float*)d_in[6];
    const float* h0     = (const float*)d_in[7];
    const float* c0     = (const float*)d_in[8];

    cudaFuncSetAttribute(lstm_persist, cudaFuncAttributeMaxDynamicSharedMemorySize, SMEM_SZ);

    cudaLaunchConfig_t cfg = {};
    cfg.gridDim = dim3(GRID, 1, 1);
    cfg.blockDim = dim3(NTHR, 1, 1);
    cfg.dynamicSmemBytes = SMEM_SZ;
    cfg.stream = 0;
    cudaLaunchAttribute at[1];
    at[0].id = cudaLaunchAttributeClusterDimension;
    at[0].val.clusterDim.x = 4; at[0].val.clusterDim.y = 1; at[0].val.clusterDim.z = 1;
    cfg.attrs = at;
    cfg.numAttrs = 1;
    cudaLaunchKernelEx(&cfg, lstm_persist, y_hist, W_ih, W_hh, b_ih, b_hh,
                       W_fc, b_fc, h0, c0, (float*)d_out);
}

// round 15
// speedup vs baseline: 1.2225x; 1.2225x over previous
#include <cuda_runtime.h>
#include <cuda_fp16.h>
#include <cstdint>

// B=256, T=512, H=1024 LSTM decoder on sm_103a (PTX baseline sm_103: no tcgen05).
// Single persistent kernel. 128 CTAs in 32 clusters of 4; 8 compute warps
// (4M x 2N, 32x32 tiles) + 1 producer warp. mma.sync m16n8k16 fp16/fp32.
// Cross-chunk register pipelining with STATIC fragment slots.
// A (h) chunks via cp.async.bulk + multicast::cluster from a pre-swizzled
// global h image, sequential chunk order. W resident in SMEM with
// gate-interleaved rows -> shfl-free epilogue.
// Publish path: bar.sync + ONE cumulative red.release.gpu (no per-thread
// membar.gpu — bar.sync gives CTA visibility, release-red is cumulative).

static constexpr int Tn = 512, Bn = 256, Hn = 1024;
static constexpr int GRID = 128, NTHR = 288;   // 8 compute warps + 1 producer
static constexpr int NCHUNK = 16;              // K chunks of 64 halfs
static constexpr int CHUNK_B = 16384;          // per-CTA A chunk: 128 rows x 128B
static constexpr int SLICE_B = 4096;           // per-rank multicast slice (32 rows)
static constexpr int IMG_CHUNK = 32768;        // image chunk: 256 rows x 128B
static constexpr int B_STR = 1032;             // W smem stride in halfs (padded)
static constexpr unsigned NPHASE = 2;          // initial + final global barriers

static constexpr int OFF_FULL = 0;             // 4 mbarriers
static constexpr int OFF_DONE = 32;            // 4 mbarriers
static constexpr int OFF_BIAS = 128;           // 64 f32
static constexpr int OFF_WIN  = 384;           // 64 f32
static constexpr int OFF_A    = 1024;          // 4 x 16KB A buffers
static constexpr int OFF_W    = OFF_A + 4 * CHUNK_B;        // 66560
static constexpr int SMEM_SZ  = OFF_W + 64 * B_STR * 2;     // 198656

__device__ __align__(1024) unsigned char g_himg[2][NCHUNK * IMG_CHUNK];
__device__ float    g_ytr[Tn * Bn];
__device__ unsigned g_bar;        // monotonic across graph replays
__device__ unsigned g_epoch;      // g_bar base for current launch
__device__ unsigned g_ready[64];  // per-cluster h-ready counters (monotonic)
__device__ unsigned g_epochR;     // g_ready base for current launch

#define SWZ(off) ((off) ^ (((off) >> 3) & 0x70))

// ---------------- helpers ----------------
__device__ __forceinline__ uint32_t smem_u32(const void* p) {
    uint32_t a;
    asm("{ .reg .u64 t; cvta.to.shared.u64 t, %1; cvt.u32.u64 %0, t; }" : "=r"(a) : "l"(p));
    return a;
}
__device__ __forceinline__ uint32_t elect_one() {
    uint32_t p;
    asm volatile("{ .reg .pred p; elect.sync _|p, 0xFFFFFFFF; selp.b32 %0, 1, 0, p; }" : "=r"(p));
    return p;
}
__device__ __forceinline__ unsigned ld_acquire_gpu(const unsigned* p) {
    unsigned v;
    asm volatile("ld.acquire.gpu.global.u32 %0, [%1];" : "=r"(v) : "l"(p) : "memory");
    return v;
}
__device__ __forceinline__ void red_release_gpu(unsigned* p, unsigned v) {
    asm volatile("red.release.gpu.global.add.u32 [%0], %1;" :: "l"(p), "r"(v) : "memory");
}
#define MBARRIER_INIT(addr, cnt) \
    asm volatile("mbarrier.init.shared.b64 [%0], %1;" :: "r"((uint32_t)(addr)), "r"((uint32_t)(cnt)) : "memory")
#define MBARRIER_EXPECT_TX(addr, tx) \
    asm volatile("mbarrier.arrive.expect_tx.shared.b64 _, [%0], %1;" :: "r"((uint32_t)(addr)), "r"((uint32_t)(tx)) : "memory")
#define ARRIVE_CLUSTER(mbar, r) \
    asm volatile("{ .reg .b32 ra; mapa.shared::cluster.u32 ra, %0, %1; " \
                 "mbarrier.arrive.shared::cluster.b64 _, [ra]; }" \
                 :: "r"((uint32_t)(mbar)), "r"((uint32_t)(r)) : "memory")

__device__ __forceinline__ void mbar_wait(uint32_t mbar, uint32_t parity) {
    asm volatile(
        "{\n\t.reg .pred P;\n\t"
        "LAB_%=:\n\t"
        "mbarrier.try_wait.parity.acquire.cta.shared::cta.b64 P, [%0], %1, 0x989680;\n\t"
        "@!P bra LAB_%=;\n\t}"
        :: "r"(mbar), "r"(parity) : "memory");
}
__device__ __forceinline__ void bulk_mcast(uint32_t dst, const void* src, uint32_t bytes,
                                           uint32_t mbar, uint16_t mask) {
    asm volatile(
        "cp.async.bulk.shared::cluster.global.mbarrier::complete_tx::bytes.multicast::cluster"
        " [%0], [%1], %2, [%3], %4;"
        :: "r"(dst), "l"(src), "r"(bytes), "r"(mbar), "h"(mask) : "memory");
}
#define CLUSTER_ARRIVE() asm volatile("barrier.cluster.arrive.aligned;" ::: "memory")
#define CLUSTER_WAIT()   asm volatile("barrier.cluster.wait.aligned;" ::: "memory")

#define LDSM_X4(r0, r1, r2, r3, addr)                                           \
    asm volatile("ldmatrix.sync.aligned.m8n8.x4.shared.b16 {%0,%1,%2,%3},[%4];" \
                 : "=r"(r0), "=r"(r1), "=r"(r2), "=r"(r3) : "r"(addr))

#define MMA16816(d, a, b0v, b1v)                                              \
    asm volatile("mma.sync.aligned.m16n8k16.row.col.f32.f16.f16.f32 "         \
                 "{%0,%1,%2,%3},{%4,%5,%6,%7},{%8,%9},{%0,%1,%2,%3};"         \
                 : "+f"((d)[0]), "+f"((d)[1]), "+f"((d)[2]), "+f"((d)[3])     \
                 : "r"((a)[0]), "r"((a)[1]), "r"((a)[2]), "r"((a)[3]),        \
                   "r"(b0v), "r"(b1v))

__device__ __forceinline__ float tanha(float x) {
    float y; asm("tanh.approx.f32 %0, %1;" : "=f"(y) : "f"(x)); return y;
}
__device__ __forceinline__ float sigt(float x) { return fmaf(tanha(0.5f * x), 0.5f, 0.5f); }

// image byte offset for (row 0..255, half-col k 0..1023)
__device__ __forceinline__ uint32_t img_off(int row, int k) {
    int kc = k >> 6, kl = k & 63;
    uint32_t local = (uint32_t)((row & 7) * 128 + kl * 2);
    return (uint32_t)(kc * IMG_CHUNK + (row >> 3) * 1024) + SWZ(local);
}

// global barrier (used ONLY at start and end): cluster.sync + leader atomic
__device__ __forceinline__ void gbar(int is_leader, unsigned target) {
    __threadfence();
    CLUSTER_ARRIVE(); CLUSTER_WAIT();
    if (is_leader) {
        atomicAdd(&g_bar, 1u);
        while (ld_acquire_gpu(&g_bar) < target) { }
    }
    CLUSTER_ARRIVE(); CLUSTER_WAIT();
}

// ---------------- the single persistent kernel ----------------
__global__ void __launch_bounds__(NTHR, 1)
lstm_persist(const float* __restrict__ y_hist, const float* __restrict__ W_ih,
             const float* __restrict__ W_hh,   const float* __restrict__ b_ih,
             const float* __restrict__ b_hh,   const float* __restrict__ W_fc,
             const float* __restrict__ b_fc,   const float* __restrict__ h0,
             const float* __restrict__ c0,     float* __restrict__ out) {
    extern __shared__ char smem[];
    const uint32_t sb = smem_u32(smem);
    float* bias_s = (float*)(smem + OFF_BIAS);
    float* win_s  = (float*)(smem + OFF_WIN);

    const int tid = threadIdx.x, lid = tid & 31, wid = tid >> 5;
    const int wm = wid >> 1, wn = wid & 1;              // compute warps: 4M x 2N
    const int bx = blockIdx.x, q = bx >> 2, rank = bx & 3;
    const int mi = q & 1, ci = (q >> 1) * 4 + rank;
    const int m0 = mi * 128, j0 = ci * 16;
    const int is_leader = (rank == 0 && tid == 0);

    const unsigned epoch = g_epoch;    // stable during the launch
    const unsigned ebR   = g_epochR;   // g_ready base for this launch

    if (tid == 0) {
        #pragma unroll
        for (int b = 0; b < 4; ++b) {
            MBARRIER_INIT(sb + OFF_FULL + b * 8, 1);
            MBARRIER_INIT(sb + OFF_DONE + b * 8, 32);   // 8 warps x 4 CTAs
        }
    }
    // gate-interleaved column map: smem W row r -> gate=(r>>3)&3, jj=(r>>5)*8+(r&7)
    if (tid < 64) {
        int gate = (tid >> 3) & 3, jj = (tid >> 5) * 8 + (tid & 7);
        int n = gate * Hn + j0 + jj;
        bias_s[tid] = b_ih[n] + b_hh[n];
        win_s[tid]  = W_ih[n];
    }
    // resident W slice with the same row map
    for (int e = tid; e < 64 * Hn / 8; e += NTHR) {
        int r = e >> 7, kg = (e & 127) << 3;
        int gate = (r >> 3) & 3, jj = (r >> 5) * 8 + (r & 7);
        const float* src = W_hh + (size_t)(gate * Hn + j0 + jj) * Hn + kg;
        float4 f0 = *(const float4*)src;
        float4 f1 = *(const float4*)(src + 4);
        __half hv[8];
        hv[0] = __float2half(f0.x); hv[1] = __float2half(f0.y);
        hv[2] = __float2half(f0.z); hv[3] = __float2half(f0.w);
        hv[4] = __float2half(f1.x); hv[5] = __float2half(f1.y);
        hv[6] = __float2half(f1.z); hv[7] = __float2half(f1.w);
        *(uint4*)(smem + OFF_W + (size_t)(r * B_STR + kg) * 2) = *(const uint4*)hv;
    }

    // -------- folded prologue: y transpose + h0 -> swizzled fp16 image --------
    for (int i = tid; i < 1024; i += NTHR) {
        int idx = bx * 1024 + i;                   // covers Tn*Bn = 131072
        int t = idx >> 8, b = idx & 255;
        g_ytr[idx] = y_hist[(size_t)b * Tn + t];
    }
    for (int i = tid; i < 256; i += NTHR) {
        int u = bx * 256 + i;                      // covers 32768 uint4 units
        int b2 = u >> 7, k = (u & 127) * 8;
        const float* s = h0 + (size_t)b2 * Hn + k;
        __half hv[8];
        #pragma unroll
        for (int j = 0; j < 8; ++j) hv[j] = __float2half(s[j]);
        *(uint4*)(g_himg[0] + img_off(b2, k)) = *(const uint4*)hv;
    }
    __syncthreads();
    gbar(is_leader, epoch + 32u);                  // prologue + mbarrier init visible

    if (wid == 8) {
        // ================= producer: flat (t, chunk) loop =================
        if (elect_one()) {
            const uint32_t src_off = (uint32_t)(mi * 16384 + rank * SLICE_B);
            unsigned n = 0;
            #pragma unroll 1
            for (int t = 0; t < Tn; ++t) {
                const unsigned char* img = g_himg[t & 1];
                const unsigned thr = ebR + 4u * (unsigned)t;
                #pragma unroll 1
                for (int i = 0; i < NCHUNK; ++i, ++n) {
                    int b = (int)(n & 3);
                    if (n >= 4) mbar_wait(sb + OFF_DONE + b * 8, ((n >> 2) - 1) & 1);
                    if (t > 0) {
                        const unsigned* rp = &g_ready[2 * i + mi];
                        while (ld_acquire_gpu(rp) < thr) { }
                    }
                    MBARRIER_EXPECT_TX(sb + OFF_FULL + b * 8, CHUNK_B);
                    bulk_mcast(sb + OFF_A + b * CHUNK_B + rank * SLICE_B,
                               img + i * IMG_CHUNK + src_off, SLICE_B,
                               sb + OFF_FULL + b * 8, 0xF);
                }
            }
        }
    } else {
        // ================= compute warps =================
        const int aRowL = lid & 15;
        const int cgB   = (lid >> 4) * 16;
        int aBase[2], aXor = 0;
        #pragma unroll
        for (int mt = 0; mt < 2; ++mt) {
            int r = wm * 32 + mt * 16 + aRowL;
            aBase[mt] = (r >> 3) * 1024 + (r & 7) * 128;
            aXor = (r & 7) * 16;
        }
        const int bRow  = (lid & 7) + ((lid >> 4) << 3);
        const int bColB = (lid & 8) ? 16 : 0;
        int bOff[2];
        #pragma unroll
        for (int np = 0; np < 2; ++np)
            bOff[np] = OFF_W + ((wn * 32 + np * 16 + bRow) * B_STR) * 2 + bColB;

        // cell ownership (shfl-free): lane owns rows (lid>>2), (lid>>2)+8 per mt,
        // h-cols j0 + wn*8 + (lid&3)*2 + {0,1}
        const int rowA = m0 + wm * 32 + (lid >> 2);
        const int jc   = j0 + wn * 8 + (lid & 3) * 2;
        float cst[8];
        #pragma unroll
        for (int mt = 0; mt < 2; ++mt)
            #pragma unroll
            for (int rr = 0; rr < 2; ++rr)
                #pragma unroll
                for (int hh = 0; hh < 2; ++hh)
                    cst[mt * 4 + rr * 2 + hh] =
                        c0[(size_t)(rowA + mt * 16 + rr * 8) * Hn + jc + hh];

        // bias / w_in into registers (step-invariant); col c = wn*32+nt*8+(lid&3)*2+hh
        float wz[4][2], bz[4][2];
        #pragma unroll
        for (int nt = 0; nt < 4; ++nt)
            #pragma unroll
            for (int hh = 0; hh < 2; ++hh) {
                int c = wn * 32 + nt * 8 + (lid & 3) * 2 + hh;
                wz[nt][hh] = win_s[c];
                bz[nt][hh] = bias_s[c];
            }

        uint32_t a0[2][4], b0v[2][4], a1[2][4], b1v[2][4];

#define LOAD_FRAGS0(ab, ksB, iB) do {                                          \
        _Pragma("unroll")                                                      \
        for (int mt = 0; mt < 2; ++mt)                                         \
            LDSM_X4(a0[mt][0], a0[mt][1], a0[mt][2], a0[mt][3],                \
                    (ab) + aBase[mt] + (((ksB) + cgB) ^ aXor));                \
        _Pragma("unroll")                                                      \
        for (int np = 0; np < 2; ++np)                                         \
            LDSM_X4(b0v[np][0], b0v[np][1], b0v[np][2], b0v[np][3],            \
                    sb + bOff[np] + (iB) * 128 + (ksB));                       \
    } while (0)

#define LOAD_FRAGS1(ab, ksB, iB) do {                                          \
        _Pragma("unroll")                                                      \
        for (int mt = 0; mt < 2; ++mt)                                         \
            LDSM_X4(a1[mt][0], a1[mt][1], a1[mt][2], a1[mt][3],                \
                    (ab) + aBase[mt] + (((ksB) + cgB) ^ aXor));                \
        _Pragma("unroll")                                                      \
        for (int np = 0; np < 2; ++np)                                         \
            LDSM_X4(b1v[np][0], b1v[np][1], b1v[np][2], b1v[np][3],            \
                    sb + bOff[np] + (iB) * 128 + (ksB));                       \
    } while (0)

#define DO_MMAS0() do {                                                        \
        _Pragma("unroll")                                                      \
        for (int mt = 0; mt < 2; ++mt)                                         \
            _Pragma("unroll")                                                  \
            for (int nt = 0; nt < 4; ++nt)                                     \
                MMA16816(d[mt][nt], a0[mt],                                    \
                         b0v[nt >> 1][(nt & 1) * 2],                           \
                         b0v[nt >> 1][(nt & 1) * 2 + 1]);                      \
    } while (0)

#define DO_MMAS1() do {                                                        \
        _Pragma("unroll")                                                      \
        for (int mt = 0; mt < 2; ++mt)                                         \
            _Pragma("unroll")                                                  \
            for (int nt = 0; nt < 4; ++nt)                                     \
                MMA16816(d[mt][nt], a1[mt],                                    \
                         b1v[nt >> 1][(nt & 1) * 2],                           \
                         b1v[nt >> 1][(nt & 1) * 2 + 1]);                      \
    } while (0)

        unsigned n = 0;
        #pragma unroll 1
        for (int t = 0; t < Tn; ++t) {
            float xA[2], xB[2];
            #pragma unroll
            for (int mt = 0; mt < 2; ++mt) {
                int rb = t * Bn + rowA + mt * 16;
                xA[mt] = __ldg(&g_ytr[rb]);
                xB[mt] = __ldg(&g_ytr[rb + 8]);
            }

            float d[2][4][4] = {};

            // step head: wait chunk 0, preload its ks0 frags into slot 0
            mbar_wait(sb + OFF_FULL + (n & 3) * 8, (n >> 2) & 1);
            LOAD_FRAGS0(sb + OFF_A + (n & 3) * CHUNK_B, 0, 0);

            // invariant at each chunk head: slot0 holds this chunk's ks0 frags
            #pragma unroll 1
            for (int i = 0; i < NCHUNK; ++i, ++n) {
                const uint32_t ab = sb + OFF_A + (n & 3) * CHUNK_B;
                LOAD_FRAGS1(ab, 32, i);  DO_MMAS0();   // ks0
                LOAD_FRAGS0(ab, 64, i);  DO_MMAS1();   // ks1
                LOAD_FRAGS1(ab, 96, i);  DO_MMAS0();   // ks2
                if (i < NCHUNK - 1) {
                    mbar_wait(sb + OFF_FULL + ((n + 1) & 3) * 8, ((n + 1) >> 2) & 1);
                    LOAD_FRAGS0(sb + OFF_A + ((n + 1) & 3) * CHUNK_B, 0, i + 1);
                }
                DO_MMAS1();                             // ks3 (slot1 consumed)
                if (elect_one()) {
                    ARRIVE_CLUSTER(sb + OFF_DONE + (n & 3) * 8, 0);
                    ARRIVE_CLUSTER(sb + OFF_DONE + (n & 3) * 8, 1);
                    ARRIVE_CLUSTER(sb + OFF_DONE + (n & 3) * 8, 2);
                    ARRIVE_CLUSTER(sb + OFF_DONE + (n & 3) * 8, 3);
                }
            }

            // epilogue (shfl-free): gate = nt, lane owns all 4 gates per cell
            unsigned char* img1 = g_himg[(t + 1) & 1];
            #pragma unroll
            for (int mt = 0; mt < 2; ++mt) {
                #pragma unroll
                for (int rr = 0; rr < 2; ++rr) {
                    float x = rr ? xB[mt] : xA[mt];
                    unsigned pk = 0;
                    #pragma unroll
                    for (int hh = 0; hh < 2; ++hh) {
                        int v = rr * 2 + hh;
                        float gi = d[mt][0][v] + x * wz[0][hh] + bz[0][hh];
                        float gf = d[mt][1][v] + x * wz[1][hh] + bz[1][hh];
                        float gg = d[mt][2][v] + x * wz[2][hh] + bz[2][hh];
                        float go = d[mt][3][v] + x * wz[3][hh] + bz[3][hh];
                        float cn = sigt(gf) * cst[mt * 4 + v] + sigt(gi) * tanha(gg);
                        cst[mt * 4 + v] = cn;
                        float hn = sigt(go) * tanha(cn);
                        pk |= (unsigned)__half_as_ushort(__float2half(hn)) << (hh * 16);
                    }
                    *(uint32_t*)(img1 + img_off(rowA + mt * 16 + rr * 8, jc)) = pk;
                }
            }

            // publish h(t+1): bar.sync (CTA visibility) + ONE cumulative
            // release-reduction to gpu scope (no per-thread membar).
            asm volatile("bar.sync 1, 256;" ::: "memory");
            if (tid == 0) red_release_gpu(&g_ready[q], 1u);
        }
#undef LOAD_FRAGS0
#undef LOAD_FRAGS1
#undef DO_MMAS0
#undef DO_MMAS1
    }

    // -------- final global barrier + folded FC --------
    gbar(is_leader, epoch + 64u);

    if (wid < 2) {
        int r = bx * 2 + wid;
        float acc = 0.0f;
        #pragma unroll
        for (int it = 0; it < 4; ++it) {
            int kc = it * 4 + (lid >> 3), u = lid & 7;
            const __half* p = (const __half*)(g_himg[0] + img_off(r, kc * 64 + u * 8));
            const float* w = W_fc + kc * 64 + u * 8;
            #pragma unroll
            for (int j = 0; j < 8; ++j) acc += __half2float(p[j]) * w[j];
        }
        #pragma unroll
        for (int o = 16; o; o >>= 1) acc += __shfl_xor_sync(~0u, acc, o);
        if (lid == 0) out[r] = acc + b_fc[0];
    }

    // advance epochs for the next launch (all adds for this launch complete)
    if (bx == 0 && tid == 0) {
        g_epoch  = epoch + 32u * NPHASE;
        g_epochR = ebR + 4u * (unsigned)Tn;
    }
}

extern "C" void kernel_launch(void* const* d_in, const int* in_sizes, int n_in,
                              void* d_out, int out_size) {
    const float* y_hist = (const float*)d_in[0];
    const float* W_ih   = (const float*)d_in[1];
    const float* W_hh   = (const float*)d_in[2];
    const float* b_ih   = (const float*)d_in[3];
    const float* b_hh   = (const float*)d_in[4];
    const float* W_fc   = (const float*)d_in[5];
    const float* b_fc   = (const float*)d_in[6];
    const float* h0     = (const float*)d_in[7];
    const float* c0     = (const float*)d_in[8];

    cudaFuncSetAttribute(lstm_persist, cudaFuncAttributeMaxDynamicSharedMemorySize, SMEM_SZ);

    cudaLaunchConfig_t cfg = {};
    cfg.gridDim = dim3(GRID, 1, 1);
    cfg.blockDim = dim3(NTHR, 1, 1);
    cfg.dynamicSmemBytes = SMEM_SZ;
    cfg.stream = 0;
    cudaLaunchAttribute at[1];
    at[0].id = cudaLaunchAttributeClusterDimension;
    at[0].val.clusterDim.x = 4; at[0].val.clusterDim.y = 1; at[0].val.clusterDim.z = 1;
    cfg.attrs = at;
    cfg.numAttrs = 1;
    cudaLaunchKernelEx(&cfg, lstm_persist, y_hist, W_ih, W_hh, b_ih, b_hh,
                       W_fc, b_fc, h0, c0, (float*)d_out);
}